// round 3
// baseline (speedup 1.0000x reference)
#include <cuda_runtime.h>
#include <cuda_bf16.h>
#include <cstdint>

// ---------------- problem constants ----------------
#define NN 100000
#define EE 1600000
#define NG 512
#define D  100      // hidden dim
#define D2 200      // concat(u, r) width
#define K1 128      // input feature dim
#define SCAN_B ((NN + 255) / 256)   // 391 scan blocks

// ---------------- device scratch (static globals: allocation-free) ----------------
__device__ int   g_deg[NN];
__device__ int   g_cursor[NN];
__device__ int   g_off[NN];
__device__ int   g_part[512];
__device__ int   g_csr[EE];
__device__ float g_dinv_s[NN];
__device__ float g_dinv_n[NN];
__device__ float g_t0[(size_t)NN * D];
__device__ float g_h1[(size_t)NN * D];
__device__ float g_t1[(size_t)NN * D];
__device__ float g_h2[(size_t)NN * D];
__device__ float g_ur[(size_t)NN * D2];
__device__ float g_sum[D];
__device__ float g_sumsq[D];
__device__ float g_Wf[D * D2];
__device__ float g_bf[D2];
__device__ float g_pool[NG * D];
__device__ float g_m1[NG * 200];
__device__ float g_m2[NG * 300];
__device__ float g_m3[NG * 200];

// ---------------- small helper kernels ----------------
__global__ void zero_kernel() {
    int i = blockIdx.x * blockDim.x + threadIdx.x;
    int stride = gridDim.x * blockDim.x;
    for (int k = i; k < NN; k += stride) { g_deg[k] = 0; g_cursor[k] = 0; }
    for (int k = i; k < NG * D; k += stride) g_pool[k] = 0.f;
    if (i < D) { g_sum[i] = 0.f; g_sumsq[i] = 0.f; }
}

__global__ void deg_kernel(const int* __restrict__ dst) {
    int e = blockIdx.x * blockDim.x + threadIdx.x;
    if (e < EE) atomicAdd(&g_deg[dst[e]], 1);
}

__global__ void dinv_kernel() {
    int i = blockIdx.x * blockDim.x + threadIdx.x;
    if (i < NN) {
        int d = g_deg[i];
        g_dinv_s[i] = rsqrtf((float)(d + 1));
        g_dinv_n[i] = (d > 0) ? rsqrtf((float)d) : 0.f;
    }
}

// two-level exclusive scan of g_deg into g_off
__global__ void scan1_kernel() {
    __shared__ int sh[256];
    int tid = threadIdx.x;
    int i = blockIdx.x * 256 + tid;
    int v = (i < NN) ? g_deg[i] : 0;
    sh[tid] = v;
    __syncthreads();
    for (int ofs = 1; ofs < 256; ofs <<= 1) {
        int t = (tid >= ofs) ? sh[tid - ofs] : 0;
        __syncthreads();
        sh[tid] += t;
        __syncthreads();
    }
    if (i < NN) g_off[i] = sh[tid] - v;
    if (tid == 255) g_part[blockIdx.x] = sh[255];
}

__global__ void scan2_kernel() {
    __shared__ int sh[512];
    int tid = threadIdx.x;
    int v = (tid < SCAN_B) ? g_part[tid] : 0;
    sh[tid] = v;
    __syncthreads();
    for (int ofs = 1; ofs < 512; ofs <<= 1) {
        int t = (tid >= ofs) ? sh[tid - ofs] : 0;
        __syncthreads();
        sh[tid] += t;
        __syncthreads();
    }
    g_part[tid] = sh[tid] - v;
}

__global__ void scan3_kernel() {
    int i = blockIdx.x * blockDim.x + threadIdx.x;
    if (i < NN) g_off[i] += g_part[i >> 8];
}

__global__ void csrfill_kernel(const int* __restrict__ src, const int* __restrict__ dst) {
    int e = blockIdx.x * blockDim.x + threadIdx.x;
    if (e < EE) {
        int d = dst[e];
        int pos = g_off[d] + atomicAdd(&g_cursor[d], 1);
        g_csr[pos] = src[e];
    }
}

// ---------------- node-level GEMM:  C[n x NC] = A[n x K] @ W[K x NC] (+bias) ----------------
// K-chunked (KC must divide K); static shared <= 48KB so no attribute opt-in needed.
template <int K, int KC, int NC>
__global__ void gemm_nodes(const float* __restrict__ A, const float* __restrict__ W,
                           const float* __restrict__ bias, float* __restrict__ C) {
    constexpr int ROWS = 64;
    constexpr int CT = (NC + 15) / 16;
    constexpr int CTP = CT * 16;
    __shared__ float Ws[KC * CTP];
    __shared__ float Xs[ROWS * (KC + 1)];
    int tid = threadIdx.x;
    int rowbase = blockIdx.x * ROWS;
    int tx = tid & 15, ty = tid >> 4;   // ty: 0..15 -> 4 rows each

    float acc[4][CT];
#pragma unroll
    for (int i = 0; i < 4; i++)
#pragma unroll
        for (int j = 0; j < CT; j++) acc[i][j] = 0.f;

    for (int k0 = 0; k0 < K; k0 += KC) {
        for (int idx = tid; idx < KC * CTP; idx += 256) {
            int k = idx / CTP, c = idx % CTP;
            Ws[idx] = (c < NC) ? W[(k0 + k) * NC + c] : 0.f;
        }
        for (int idx = tid; idx < ROWS * KC; idx += 256) {
            int r = idx / KC, k = idx % KC;
            int gr = rowbase + r;
            Xs[r * (KC + 1) + k] = (gr < NN) ? A[(size_t)gr * K + k0 + k] : 0.f;
        }
        __syncthreads();

#pragma unroll 2
        for (int k = 0; k < KC; k++) {
            float a[4];
#pragma unroll
            for (int i = 0; i < 4; i++) a[i] = Xs[(ty * 4 + i) * (KC + 1) + k];
#pragma unroll
            for (int j = 0; j < CT; j++) {
                float w = Ws[k * CTP + tx + j * 16];
#pragma unroll
                for (int i = 0; i < 4; i++) acc[i][j] = fmaf(a[i], w, acc[i][j]);
            }
        }
        __syncthreads();
    }

#pragma unroll
    for (int i = 0; i < 4; i++) {
        int gr = rowbase + ty * 4 + i;
        if (gr >= NN) continue;
#pragma unroll
        for (int j = 0; j < CT; j++) {
            int c = tx + j * 16;
            if (c < NC) {
                float v = acc[i][j];
                if (bias) v += bias[c];
                C[(size_t)gr * NC + c] = v;
            }
        }
    }
}

// ---------------- GCN propagation with self loops, pull-based, fused bias+relu ----------------
__global__ void prop_self_kernel(const float* __restrict__ T, const float* __restrict__ bias,
                                 float* __restrict__ out) {
    int warp = (blockIdx.x * blockDim.x + threadIdx.x) >> 5;
    if (warp >= NN) return;
    int lane = threadIdx.x & 31;
    int i = warp;
    int start = g_off[i];
    int cnt = g_deg[i];
    float di = g_dinv_s[i];
    const int c0 = lane, c1 = lane + 32, c2 = lane + 64, c3 = lane + 96;
    bool has3 = (lane < D - 96);
    float a0 = 0.f, a1 = 0.f, a2 = 0.f, a3 = 0.f;
    int e = 0;
    for (; e + 2 <= cnt; e += 2) {
        int j0 = g_csr[start + e];
        int j1 = g_csr[start + e + 1];
        float w0 = g_dinv_s[j0], w1 = g_dinv_s[j1];
        const float* r0 = T + (size_t)j0 * D;
        const float* r1 = T + (size_t)j1 * D;
        a0 = fmaf(w0, r0[c0], a0); a1 = fmaf(w0, r0[c1], a1); a2 = fmaf(w0, r0[c2], a2);
        a0 = fmaf(w1, r1[c0], a0); a1 = fmaf(w1, r1[c1], a1); a2 = fmaf(w1, r1[c2], a2);
        if (has3) { a3 = fmaf(w0, r0[c3], a3); a3 = fmaf(w1, r1[c3], a3); }
    }
    if (e < cnt) {
        int j = g_csr[start + e];
        float w = g_dinv_s[j];
        const float* r = T + (size_t)j * D;
        a0 = fmaf(w, r[c0], a0); a1 = fmaf(w, r[c1], a1); a2 = fmaf(w, r[c2], a2);
        if (has3) a3 = fmaf(w, r[c3], a3);
    }
    const float* ri = T + (size_t)i * D;
    a0 = fmaf(di, ri[c0], a0); a1 = fmaf(di, ri[c1], a1); a2 = fmaf(di, ri[c2], a2);
    if (has3) a3 = fmaf(di, ri[c3], a3);
    float* o = out + (size_t)i * D;
    o[c0] = fmaxf(fmaf(di, a0, bias[c0]), 0.f);
    o[c1] = fmaxf(fmaf(di, a1, bias[c1]), 0.f);
    o[c2] = fmaxf(fmaf(di, a2, bias[c2]), 0.f);
    if (has3) o[c3] = fmaxf(fmaf(di, a3, bias[c3]), 0.f);
}

// ---------------- BatchNorm stats (column sums / sumsqs of g_h2) ----------------
__global__ void bn_stats_kernel() {
    __shared__ float ss[D], sq[D];
    for (int c = threadIdx.x; c < D; c += blockDim.x) { ss[c] = 0.f; sq[c] = 0.f; }
    __syncthreads();
    const int total = NN * D;
    for (int idx = blockIdx.x * blockDim.x + threadIdx.x; idx < total;
         idx += gridDim.x * blockDim.x) {
        float v = g_h2[idx];
        int c = idx % D;
        atomicAdd(&ss[c], v);
        atomicAdd(&sq[c], v * v);
    }
    __syncthreads();
    for (int c = threadIdx.x; c < D; c += blockDim.x) {
        atomicAdd(&g_sum[c], ss[c]);
        atomicAdd(&g_sumsq[c], sq[c]);
    }
}

// ---------------- fold BatchNorm affine into ARMA weights ----------------
// h = h2*s + t  =>  h@Wa = h2@(diag(s)Wa) + t@Wa
__global__ void fold_kernel(const float* __restrict__ gamma, const float* __restrict__ beta,
                            const float* __restrict__ Wa_init, const float* __restrict__ Wa_root,
                            const float* __restrict__ ba) {
    __shared__ float s[D], t[D];
    int tid = threadIdx.x;
    if (tid < D) {
        float mu = g_sum[tid] * (1.f / NN);
        float var = g_sumsq[tid] * (1.f / NN) - mu * mu;
        float rs = rsqrtf(var + 1e-5f);
        float sv = gamma[tid] * rs;
        s[tid] = sv;
        t[tid] = beta[tid] - mu * sv;
    }
    __syncthreads();
    for (int idx = tid; idx < D * D2; idx += blockDim.x) {
        int k = idx / D2, c = idx % D2;
        float w = (c < D) ? Wa_init[k * D + c] : Wa_root[k * D + (c - D)];
        g_Wf[idx] = s[k] * w;
    }
    for (int c = tid; c < D2; c += blockDim.x) {
        float acc;
        if (c < D) {
            acc = 0.f;
            for (int k = 0; k < D; k++) acc = fmaf(t[k], Wa_init[k * D + c], acc);
        } else {
            int cc = c - D;
            acc = ba[cc];
            for (int k = 0; k < D; k++) acc = fmaf(t[k], Wa_root[k * D + cc], acc);
        }
        g_bf[c] = acc;
    }
}

// ---------------- ARMA prop (no self loops) + root add + relu + pooled scatter ----------------
__global__ void arma_pool_kernel(const int* __restrict__ batch) {
    int warp = (blockIdx.x * blockDim.x + threadIdx.x) >> 5;
    if (warp >= NN) return;
    int lane = threadIdx.x & 31;
    int i = warp;
    int start = g_off[i];
    int cnt = g_deg[i];
    float di = g_dinv_n[i];
    const int c0 = lane, c1 = lane + 32, c2 = lane + 64, c3 = lane + 96;
    bool has3 = (lane < D - 96);
    float a0 = 0.f, a1 = 0.f, a2 = 0.f, a3 = 0.f;
    int e = 0;
    for (; e + 2 <= cnt; e += 2) {
        int j0 = g_csr[start + e];
        int j1 = g_csr[start + e + 1];
        float w0 = g_dinv_n[j0], w1 = g_dinv_n[j1];
        const float* r0 = g_ur + (size_t)j0 * D2;
        const float* r1 = g_ur + (size_t)j1 * D2;
        a0 = fmaf(w0, r0[c0], a0); a1 = fmaf(w0, r0[c1], a1); a2 = fmaf(w0, r0[c2], a2);
        a0 = fmaf(w1, r1[c0], a0); a1 = fmaf(w1, r1[c1], a1); a2 = fmaf(w1, r1[c2], a2);
        if (has3) { a3 = fmaf(w0, r0[c3], a3); a3 = fmaf(w1, r1[c3], a3); }
    }
    if (e < cnt) {
        int j = g_csr[start + e];
        float w = g_dinv_n[j];
        const float* r = g_ur + (size_t)j * D2;
        a0 = fmaf(w, r[c0], a0); a1 = fmaf(w, r[c1], a1); a2 = fmaf(w, r[c2], a2);
        if (has3) a3 = fmaf(w, r[c3], a3);
    }
    const float* ri = g_ur + (size_t)i * D2 + D;   // root part
    float v0 = fmaxf(fmaf(di, a0, ri[c0]), 0.f);
    float v1 = fmaxf(fmaf(di, a1, ri[c1]), 0.f);
    float v2 = fmaxf(fmaf(di, a2, ri[c2]), 0.f);
    float* p = g_pool + (size_t)batch[i] * D;
    atomicAdd(&p[c0], v0);
    atomicAdd(&p[c1], v1);
    atomicAdd(&p[c2], v2);
    if (has3) {
        float v3 = fmaxf(fmaf(di, a3, ri[c3]), 0.f);
        atomicAdd(&p[c3], v3);
    }
}

// ---------------- small MLP GEMM (row per block) ----------------
template <int K, int NC, bool RELU>
__global__ void mlp_gemm(const float* __restrict__ A, const float* __restrict__ W,
                         const float* __restrict__ b, float* __restrict__ C) {
    __shared__ float As[K];
    int r = blockIdx.x;
    for (int k = threadIdx.x; k < K; k += blockDim.x) As[k] = A[r * K + k];
    __syncthreads();
    for (int c = threadIdx.x; c < NC; c += blockDim.x) {
        float acc = b[c];
#pragma unroll 4
        for (int k = 0; k < K; k++) acc = fmaf(As[k], W[k * NC + c], acc);
        C[r * NC + c] = RELU ? fmaxf(acc, 0.f) : acc;
    }
}

// ---------------- host helper: real device address of a __device__ symbol ----------------
static float* symaddr(const void* sym) {
    void* p = nullptr;
    cudaGetSymbolAddress(&p, sym);
    return (float*)p;
}

// ---------------- launcher ----------------
extern "C" void kernel_launch(void* const* d_in, const int* in_sizes, int n_in,
                              void* d_out, int out_size) {
    const float* x       = (const float*)d_in[0];
    const int*   src     = (const int*)d_in[1];
    const int*   dst     = (const int*)d_in[2];
    const int*   batch   = (const int*)d_in[3];
    const float* W1      = (const float*)d_in[4];
    const float* b1      = (const float*)d_in[5];
    const float* W2      = (const float*)d_in[6];
    const float* b2      = (const float*)d_in[7];
    const float* gamma   = (const float*)d_in[8];
    const float* beta    = (const float*)d_in[9];
    const float* Wa_init = (const float*)d_in[10];
    const float* Wa_root = (const float*)d_in[11];
    const float* ba      = (const float*)d_in[12];
    const float* Wf1     = (const float*)d_in[13];
    const float* bf1     = (const float*)d_in[14];
    const float* Wf2     = (const float*)d_in[15];
    const float* bf2     = (const float*)d_in[16];
    const float* Wf3     = (const float*)d_in[17];
    const float* bf3     = (const float*)d_in[18];
    const float* Wf4     = (const float*)d_in[19];
    const float* bf4     = (const float*)d_in[20];
    float* out = (float*)d_out;

    // real device addresses of the scratch buffers (NOT the host shadows!)
    float* p_t0   = symaddr(g_t0);
    float* p_h1   = symaddr(g_h1);
    float* p_t1   = symaddr(g_t1);
    float* p_h2   = symaddr(g_h2);
    float* p_ur   = symaddr(g_ur);
    float* p_Wf   = symaddr(g_Wf);
    float* p_bf   = symaddr(g_bf);
    float* p_pool = symaddr(g_pool);
    float* p_m1   = symaddr(g_m1);
    float* p_m2   = symaddr(g_m2);
    float* p_m3   = symaddr(g_m3);

    const int GB_N = (NN + 255) / 256;       // 391
    const int GB_E = (EE + 255) / 256;       // 6250
    const int GB_W = (NN * 32 + 255) / 256;  // 12500 (warp per node)
    const int GB_G = (NN + 63) / 64;         // 1563

    zero_kernel<<<GB_N, 256>>>();
    deg_kernel<<<GB_E, 256>>>(dst);
    dinv_kernel<<<GB_N, 256>>>();
    scan1_kernel<<<SCAN_B, 256>>>();
    scan2_kernel<<<1, 512>>>();
    scan3_kernel<<<GB_N, 256>>>();
    csrfill_kernel<<<GB_E, 256>>>(src, dst);

    // SGConv 1: t0 = x @ W1 ; h1 = relu(prop_self(t0) + b1)
    gemm_nodes<K1, 64, D><<<GB_G, 256>>>(x, W1, nullptr, p_t0);
    prop_self_kernel<<<GB_W, 256>>>(p_t0, b1, p_h1);

    // SGConv 2: t1 = h1 @ W2 ; h2 = relu(prop_self(t1) + b2)
    gemm_nodes<D, 50, D><<<GB_G, 256>>>(p_h1, W2, nullptr, p_t1);
    prop_self_kernel<<<GB_W, 256>>>(p_t1, b2, p_h2);

    // BatchNorm stats + fold into ARMA weights
    bn_stats_kernel<<<512, 256>>>();
    fold_kernel<<<1, 256>>>(gamma, beta, Wa_init, Wa_root, ba);

    // ARMA: ur = h2 @ Wf + bf  (u = cols 0..99, r = cols 100..199)
    gemm_nodes<D, 25, D2><<<GB_G, 256>>>(p_h2, p_Wf, p_bf, p_ur);

    // a = relu(prop_noself(u) + r), pooled by graph id (fused)
    arma_pool_kernel<<<GB_W, 256>>>(batch);

    // MLP head on [512, 100]
    mlp_gemm<100, 200, true><<<NG, 256>>>(p_pool, Wf1, bf1, p_m1);
    mlp_gemm<200, 300, true><<<NG, 256>>>(p_m1, Wf2, bf2, p_m2);
    mlp_gemm<300, 200, true><<<NG, 256>>>(p_m2, Wf3, bf3, p_m3);
    mlp_gemm<200, 1, false><<<NG, 32>>>(p_m3, Wf4, bf4, out);
}